// round 1
// baseline (speedup 1.0000x reference)
#include <cuda_runtime.h>
#include <math.h>

#define EPSF 1e-6f

#define BATCH 8192
#define INDIM 512
#define HIDDIM 1024
#define ACTDIM 64

// ------------------------- scratch (no cudaMalloc allowed) -------------------------
__device__ float g_enc [(size_t)BATCH * HIDDIM];
__device__ float g_t1  [(size_t)BATCH * HIDDIM];
__device__ float g_corr[(size_t)BATCH * HIDDIM];
__device__ float g_attn[(size_t)BATCH * HIDDIM];
__device__ float g_norm[BATCH];
__device__ float g_term[BATCH];
__device__ float g_S   [(size_t)BATCH * BATCH];

// ------------------------- generic NN GEMM with epilogues -------------------------
// C[M,N] = epi(A[M,K] @ B[K,N])
// EPI: 0 = none, 1 = relu(x + bias[n]), 2 = tanh(x + bias[n]) + extra[m,n], 3 = x + bias[n]
// Requires: M % BM == 0, N % BN == 0, K % BK == 0 (true for all calls here).
template<int BM, int BN, int BK, int TM, int TN, int EPI>
__global__ void __launch_bounds__(256)
gemm_nn(const float* __restrict__ A, const float* __restrict__ B,
        float* __restrict__ C, int M, int N, int K,
        const float* __restrict__ bias, const float* __restrict__ extra)
{
    __shared__ float As[BK][BM + 4];
    __shared__ float Bs[BK][BN + 4];

    const int tid = threadIdx.x;
    const int m0 = blockIdx.y * BM;
    const int n0 = blockIdx.x * BN;
    constexpr int TX = BN / TN;          // threads along N
    const int tx = tid % TX;
    const int ty = tid / TX;

    float acc[TM][TN] = {};

    constexpr int LA = BM * BK / (4 * 256);   // float4 loads per thread for A tile
    constexpr int LB = BK * BN / (4 * 256);   // float4 loads per thread for B tile

    for (int k0 = 0; k0 < K; k0 += BK) {
        // A tile (BM x BK), stored transposed As[k][m]
        #pragma unroll
        for (int i = 0; i < LA; i++) {
            int f4  = tid + i * 256;
            int row = f4 / (BK / 4);
            int c4  = f4 % (BK / 4);
            float4 v = *reinterpret_cast<const float4*>(&A[(size_t)(m0 + row) * K + k0 + c4 * 4]);
            As[c4 * 4 + 0][row] = v.x;
            As[c4 * 4 + 1][row] = v.y;
            As[c4 * 4 + 2][row] = v.z;
            As[c4 * 4 + 3][row] = v.w;
        }
        // B tile (BK x BN), direct Bs[k][n]
        #pragma unroll
        for (int i = 0; i < LB; i++) {
            int f4  = tid + i * 256;
            int row = f4 / (BN / 4);
            int c4  = f4 % (BN / 4);
            float4 v = *reinterpret_cast<const float4*>(&B[(size_t)(k0 + row) * N + n0 + c4 * 4]);
            *reinterpret_cast<float4*>(&Bs[row][c4 * 4]) = v;
        }
        __syncthreads();

        #pragma unroll
        for (int k = 0; k < BK; k++) {
            float a[TM], b[TN];
            #pragma unroll
            for (int i = 0; i < TM; i++) a[i] = As[k][ty * TM + i];
            #pragma unroll
            for (int j = 0; j < TN; j++) b[j] = Bs[k][tx * TN + j];
            #pragma unroll
            for (int i = 0; i < TM; i++)
                #pragma unroll
                for (int j = 0; j < TN; j++)
                    acc[i][j] = fmaf(a[i], b[j], acc[i][j]);
        }
        __syncthreads();
    }

    #pragma unroll
    for (int i = 0; i < TM; i++) {
        int m = m0 + ty * TM + i;
        #pragma unroll
        for (int j = 0; j < TN; j++) {
            int n = n0 + tx * TN + j;
            float v = acc[i][j];
            if constexpr (EPI == 1) v = fmaxf(v + bias[n], 0.0f);
            if constexpr (EPI == 2) v = tanhf(v + bias[n]) + extra[(size_t)m * N + n];
            if constexpr (EPI == 3) v = v + bias[n];
            C[(size_t)m * N + n] = v;
        }
    }
}

// ------------------------- A @ A^T GEMM with hyperbolic-distance epilogue -------------------------
// S[m,n] = -arccosh(max(1 + 2c*d2/(term_m*term_n), 1+eps) + eps) / sqrt(c)
// where d2 = max(norm_m + norm_n - 2*dot(corr_m, corr_n), 0)
template<int BM, int BN, int BK, int TM, int TN>
__global__ void __launch_bounds__(256)
gemm_nt_dist(const float* __restrict__ Acorr, float* __restrict__ S,
             int M, int N, int K,
             const float* __restrict__ norm, const float* __restrict__ term,
             const float* __restrict__ cptr)
{
    __shared__ float As[BK][BM + 4];
    __shared__ float Bs[BK][BN + 4];

    const int tid = threadIdx.x;
    const int m0 = blockIdx.y * BM;
    const int n0 = blockIdx.x * BN;
    constexpr int TX = BN / TN;
    const int tx = tid % TX;
    const int ty = tid / TX;

    float acc[TM][TN] = {};

    constexpr int LA = BM * BK / (4 * 256);
    constexpr int LBt = BN * BK / (4 * 256);

    for (int k0 = 0; k0 < K; k0 += BK) {
        #pragma unroll
        for (int i = 0; i < LA; i++) {
            int f4  = tid + i * 256;
            int row = f4 / (BK / 4);
            int c4  = f4 % (BK / 4);
            float4 v = *reinterpret_cast<const float4*>(&Acorr[(size_t)(m0 + row) * K + k0 + c4 * 4]);
            As[c4 * 4 + 0][row] = v.x;
            As[c4 * 4 + 1][row] = v.y;
            As[c4 * 4 + 2][row] = v.z;
            As[c4 * 4 + 3][row] = v.w;
        }
        // B^T tile: rows are "n" indices into corr
        #pragma unroll
        for (int i = 0; i < LBt; i++) {
            int f4  = tid + i * 256;
            int row = f4 / (BK / 4);
            int c4  = f4 % (BK / 4);
            float4 v = *reinterpret_cast<const float4*>(&Acorr[(size_t)(n0 + row) * K + k0 + c4 * 4]);
            Bs[c4 * 4 + 0][row] = v.x;
            Bs[c4 * 4 + 1][row] = v.y;
            Bs[c4 * 4 + 2][row] = v.z;
            Bs[c4 * 4 + 3][row] = v.w;
        }
        __syncthreads();

        #pragma unroll
        for (int k = 0; k < BK; k++) {
            float a[TM], b[TN];
            #pragma unroll
            for (int i = 0; i < TM; i++) a[i] = As[k][ty * TM + i];
            #pragma unroll
            for (int j = 0; j < TN; j++) b[j] = Bs[k][tx * TN + j];
            #pragma unroll
            for (int i = 0; i < TM; i++)
                #pragma unroll
                for (int j = 0; j < TN; j++)
                    acc[i][j] = fmaf(a[i], b[j], acc[i][j]);
        }
        __syncthreads();
    }

    const float cc  = fmaxf(cptr[0], EPSF);
    const float isc = rsqrtf(cc);
    const float two_cc = 2.0f * cc;

    #pragma unroll
    for (int i = 0; i < TM; i++) {
        int m = m0 + ty * TM + i;
        float nm = norm[m];
        float tm = term[m];
        #pragma unroll
        for (int j = 0; j < TN; j++) {
            int n = n0 + tx * TN + j;
            float g  = acc[i][j];
            float d2 = fmaxf(nm + norm[n] - 2.0f * g, 0.0f);
            float arg = 1.0f + two_cc * d2 / (tm * term[n]);
            arg = fmaxf(arg, 1.0f + EPSF) + EPSF;
            S[(size_t)m * N + n] = -acoshf(arg) * isc;
        }
    }
}

// ------------------------- row squared norms + term -------------------------
__global__ void row_norms(const float* __restrict__ X, float* __restrict__ norm,
                          float* __restrict__ term, const float* __restrict__ cptr,
                          int B, int D)
{
    int warp = (blockIdx.x * blockDim.x + threadIdx.x) >> 5;
    int lane = threadIdx.x & 31;
    if (warp >= B) return;
    const float* x = X + (size_t)warp * D;
    float s = 0.0f;
    for (int k = lane; k < D; k += 32) { float v = x[k]; s = fmaf(v, v, s); }
    #pragma unroll
    for (int o = 16; o; o >>= 1) s += __shfl_xor_sync(0xFFFFFFFFu, s, o);
    if (lane == 0) {
        norm[warp] = s;
        float cc = fmaxf(cptr[0], EPSF);
        term[warp] = fmaxf(1.0f - cc * s, EPSF);
    }
}

// ------------------------- row softmax over [B, N] (N = 8192), in place -------------------------
__global__ void __launch_bounds__(256)
softmax_rows(float* __restrict__ S, int N)
{
    __shared__ float buf[BATCH];   // 32 KB row cache
    __shared__ float red[32];
    const int tid = threadIdx.x;
    float* Sr = S + (size_t)blockIdx.x * N;

    float mx = -3.4e38f;
    for (int i = tid; i < N; i += 256) { float v = Sr[i]; buf[i] = v; mx = fmaxf(mx, v); }
    #pragma unroll
    for (int o = 16; o; o >>= 1) mx = fmaxf(mx, __shfl_xor_sync(0xFFFFFFFFu, mx, o));
    if ((tid & 31) == 0) red[tid >> 5] = mx;
    __syncthreads();
    if (tid < 32) {
        float v = (tid < 8) ? red[tid] : -3.4e38f;
        #pragma unroll
        for (int o = 4; o; o >>= 1) v = fmaxf(v, __shfl_xor_sync(0xFFFFFFFFu, v, o));
        if (tid == 0) red[0] = v;
    }
    __syncthreads();
    mx = red[0];

    float sum = 0.0f;
    for (int i = tid; i < N; i += 256) { float e = expf(buf[i] - mx); buf[i] = e; sum += e; }
    __syncthreads();   // all reads of red[0] done before re-writing red
    #pragma unroll
    for (int o = 16; o; o >>= 1) sum += __shfl_xor_sync(0xFFFFFFFFu, sum, o);
    if ((tid & 31) == 0) red[tid >> 5] = sum;
    __syncthreads();
    if (tid < 32) {
        float v = (tid < 8) ? red[tid] : 0.0f;
        #pragma unroll
        for (int o = 4; o; o >>= 1) v += __shfl_xor_sync(0xFFFFFFFFu, v, o);
        if (tid == 0) red[0] = v;
    }
    __syncthreads();
    float inv = 1.0f / red[0];
    for (int i = tid; i < N; i += 256) Sr[i] = buf[i] * inv;
}

// ------------------------- heads epilogue: softmax(64) + risk sigmoid -------------------------
__global__ void heads_epilogue(const float* __restrict__ logits,
                               const float* __restrict__ attn,
                               const float* __restrict__ W_risk,
                               const float* __restrict__ b_risk,
                               float* __restrict__ probs,
                               float* __restrict__ risk,
                               int B, int D)
{
    int warp = (blockIdx.x * blockDim.x + threadIdx.x) >> 5;
    int lane = threadIdx.x & 31;
    if (warp >= B) return;

    // risk = sigmoid(attn_row . W_risk + b_risk)
    const float* ar = attn + (size_t)warp * D;
    float s = 0.0f;
    for (int k = lane; k < D; k += 32) s = fmaf(ar[k], W_risk[k], s);
    #pragma unroll
    for (int o = 16; o; o >>= 1) s += __shfl_xor_sync(0xFFFFFFFFu, s, o);
    if (lane == 0) risk[warp] = 1.0f / (1.0f + expf(-(s + b_risk[0])));

    // softmax over 64 logits (two values per lane)
    const float* lr = logits + (size_t)warp * ACTDIM;
    float v0 = lr[lane], v1 = lr[lane + 32];
    float mx = fmaxf(v0, v1);
    #pragma unroll
    for (int o = 16; o; o >>= 1) mx = fmaxf(mx, __shfl_xor_sync(0xFFFFFFFFu, mx, o));
    float e0 = expf(v0 - mx), e1 = expf(v1 - mx);
    float ss = e0 + e1;
    #pragma unroll
    for (int o = 16; o; o >>= 1) ss += __shfl_xor_sync(0xFFFFFFFFu, ss, o);
    float inv = 1.0f / ss;
    probs[(size_t)warp * ACTDIM + lane]      = e0 * inv;
    probs[(size_t)warp * ACTDIM + lane + 32] = e1 * inv;
}

// ------------------------- launch -------------------------
extern "C" void kernel_launch(void* const* d_in, const int* in_sizes, int n_in,
                              void* d_out, int out_size)
{
    const float* state   = (const float*)d_in[0];
    const float* W_enc   = (const float*)d_in[1];
    const float* b_enc   = (const float*)d_in[2];
    const float* cov     = (const float*)d_in[3];
    const float* W_phase = (const float*)d_in[4];
    const float* b_phase = (const float*)d_in[5];
    const float* cptr    = (const float*)d_in[6];
    const float* W_actor = (const float*)d_in[7];
    const float* b_actor = (const float*)d_in[8];
    const float* W_risk  = (const float*)d_in[9];
    const float* b_risk  = (const float*)d_in[10];

    float* out    = (float*)d_out;
    float* logits = out;                                    // [B, 64]
    float* probs  = out + (size_t)BATCH * ACTDIM;           // [B, 64]
    float* risk   = out + (size_t)2 * BATCH * ACTDIM;       // [B, 1]

    float *enc, *t1, *corr, *attn, *nrm, *term, *S;
    cudaGetSymbolAddress((void**)&enc,  g_enc);
    cudaGetSymbolAddress((void**)&t1,   g_t1);
    cudaGetSymbolAddress((void**)&corr, g_corr);
    cudaGetSymbolAddress((void**)&attn, g_attn);
    cudaGetSymbolAddress((void**)&nrm,  g_norm);
    cudaGetSymbolAddress((void**)&term, g_term);
    cudaGetSymbolAddress((void**)&S,    g_S);

    // 1) enc = relu(state @ W_enc + b_enc)   [8192,512]x[512,1024]
    gemm_nn<128,128,16,8,8,1><<<dim3(HIDDIM/128, BATCH/128), 256>>>(
        state, W_enc, enc, BATCH, HIDDIM, INDIM, b_enc, nullptr);

    // 2) t1 = enc @ cov   [8192,1024]x[1024,1024]
    gemm_nn<128,128,16,8,8,0><<<dim3(HIDDIM/128, BATCH/128), 256>>>(
        enc, cov, t1, BATCH, HIDDIM, HIDDIM, nullptr, nullptr);

    // 3) corr = tanh(t1 @ W_phase + b_phase) + enc
    gemm_nn<128,128,16,8,8,2><<<dim3(HIDDIM/128, BATCH/128), 256>>>(
        t1, W_phase, corr, BATCH, HIDDIM, HIDDIM, b_phase, enc);

    // 4) per-row squared norms + term
    row_norms<<<BATCH/8, 256>>>(corr, nrm, term, cptr, BATCH, HIDDIM);

    // 5) S = -dist(corr, corr) via Gram matrix epilogue  [8192,8192]
    gemm_nt_dist<128,128,16,8,8><<<dim3(BATCH/128, BATCH/128), 256>>>(
        corr, S, BATCH, BATCH, HIDDIM, nrm, term, cptr);

    // 6) P = softmax_rows(S) in place
    softmax_rows<<<BATCH, 256>>>(S, BATCH);

    // 7) attn = P @ corr   [8192,8192]x[8192,1024]
    gemm_nn<128,128,16,8,8,0><<<dim3(HIDDIM/128, BATCH/128), 256>>>(
        S, corr, attn, BATCH, HIDDIM, BATCH, nullptr, nullptr);

    // 8) logits = attn @ W_actor + b_actor  [8192,1024]x[1024,64] -> directly into out
    gemm_nn<128,64,16,8,4,3><<<dim3(ACTDIM/64, BATCH/128), 256>>>(
        attn, W_actor, logits, BATCH, ACTDIM, HIDDIM, b_actor, nullptr);

    // 9) probs + risk
    heads_epilogue<<<BATCH/8, 256>>>(logits, attn, W_risk, b_risk, probs, risk, BATCH, HIDDIM);
}